// round 16
// baseline (speedup 1.0000x reference)
#include <cuda_runtime.h>
#include <cuda_fp16.h>
#include <math.h>

#define BB 16
#define CC 256
#define SS 1024
#define NH 4
#define DK 64
#define NQKV 768

#define NX   (BB * CC * SS)
#define NWP  (CC * NQKV)
#define NWO  (NH * DK * CC)

// log2(e)/8 folded into Q
#define QSCALE 0.1803368801111244f

__device__ __half g_Xb[NX];
__device__ __half g_Wpb[NWP];
__device__ __half g_Wob[NWO];
__device__ __half g_Q[BB * NH * SS * DK];   // [B,H,S,D], pre-scaled
__device__ __half g_K[BB * NH * SS * DK];
__device__ __half g_V[BB * NH * SS * DK];
__device__ __half g_O[BB * SS * CC];

// ---------------------------------------------------------------------------
__device__ __forceinline__ unsigned sptr(const void* p) {
    return (unsigned)__cvta_generic_to_shared(p);
}
__device__ __forceinline__ unsigned packh(float lo, float hi) {
    unsigned r;
    asm("cvt.rn.f16x2.f32 %0, %1, %2;" : "=r"(r) : "f"(hi), "f"(lo));
    return r;
}
__device__ __forceinline__ unsigned ex2h2(unsigned x) {
    unsigned r;
    asm("ex2.approx.f16x2 %0, %1;" : "=r"(r) : "r"(x));
    return r;
}
__device__ __forceinline__ void ldsm4(unsigned& r0, unsigned& r1, unsigned& r2,
                                      unsigned& r3, unsigned addr) {
    asm volatile("ldmatrix.sync.aligned.m8n8.x4.shared.b16 {%0,%1,%2,%3}, [%4];"
                 : "=r"(r0), "=r"(r1), "=r"(r2), "=r"(r3) : "r"(addr));
}
__device__ __forceinline__ void ldsm4t(unsigned& r0, unsigned& r1, unsigned& r2,
                                       unsigned& r3, unsigned addr) {
    asm volatile("ldmatrix.sync.aligned.m8n8.x4.trans.shared.b16 {%0,%1,%2,%3}, [%4];"
                 : "=r"(r0), "=r"(r1), "=r"(r2), "=r"(r3) : "r"(addr));
}
__device__ __forceinline__ void mma_f16(float* c,
    unsigned a0, unsigned a1, unsigned a2, unsigned a3, unsigned b0, unsigned b1) {
    asm volatile(
        "mma.sync.aligned.m16n8k16.row.col.f32.f16.f16.f32 "
        "{%0,%1,%2,%3}, {%4,%5,%6,%7}, {%8,%9}, {%0,%1,%2,%3};"
        : "+f"(c[0]), "+f"(c[1]), "+f"(c[2]), "+f"(c[3])
        : "r"(a0), "r"(a1), "r"(a2), "r"(a3), "r"(b0), "r"(b1));
}
// fp16-accumulate variant: C/D are 2 regs of f16x2 (already P-fragment layout)
__device__ __forceinline__ void mma_f16acc(unsigned* c,
    unsigned a0, unsigned a1, unsigned a2, unsigned a3, unsigned b0, unsigned b1) {
    asm volatile(
        "mma.sync.aligned.m16n8k16.row.col.f16.f16.f16.f16 "
        "{%0,%1}, {%2,%3,%4,%5}, {%6,%7}, {%0,%1};"
        : "+r"(c[0]), "+r"(c[1])
        : "r"(a0), "r"(a1), "r"(a2), "r"(a3), "r"(b0), "r"(b1));
}
__device__ __forceinline__ void cp16(unsigned dst, const void* src) {
    asm volatile("cp.async.cg.shared.global [%0], [%1], 16;\n" :: "r"(dst), "l"(src));
}
#define CP_COMMIT() asm volatile("cp.async.commit_group;\n" ::: "memory")
#define CP_WAIT0()  asm volatile("cp.async.wait_group 0;\n" ::: "memory")

// ---------------------------------------------------------------------------
// Kernel 0: fp32 -> fp16 conversion
// ---------------------------------------------------------------------------
__global__ __launch_bounds__(256) void convert_kernel(
    const float* __restrict__ x, const float* __restrict__ wp,
    const float* __restrict__ wo)
{
    long long base = ((long long)blockIdx.x * 256 + threadIdx.x) * 4;
    const float* src;
    __half* dst;
    long long off;
    if (base < NX)             { src = x;  dst = g_Xb;  off = base; }
    else if (base < NX + NWP)  { src = wp; dst = g_Wpb; off = base - NX; }
    else                       { src = wo; dst = g_Wob; off = base - NX - NWP; }
    float4 t = *(const float4*)&src[off];
    *(uint2*)&dst[off] = make_uint2(packh(t.x, t.y), packh(t.z, t.w));
}

// ---------------------------------------------------------------------------
// Kernel 1: QKV projection. 128x128x32 tiles, 2-stage cp.async, 8 warps.
// ---------------------------------------------------------------------------
__global__ __launch_bounds__(256) void qkv_gemm_kernel(const float* __restrict__ bp)
{
    __shared__ __align__(16) __half As[2][32 * 136];
    __shared__ __align__(16) __half Bs[2][32 * 136];

    const int tid = threadIdx.x, lane = tid & 31, w = tid >> 5;
    const int wm = w & 3, wn = w >> 2;
    const int g = lane >> 2, c = lane & 3;
    const int m0 = blockIdx.y * 128, n0 = blockIdx.x * 128;
    const int b = m0 >> 10, s0 = m0 & 1023;

    float acc[2][8][4] = {};

    #define QKV_LOAD(st, k0)                                                     \
        {                                                                        \
            _Pragma("unroll")                                                    \
            for (int r = 0; r < 2; r++) {                                        \
                int i = tid + r * 256;                                           \
                int k = i >> 4, m8 = (i & 15) * 8;                               \
                cp16(sptr(&As[st][k * 136 + m8]),                                \
                     &g_Xb[(size_t)(b * CC + (k0) + k) * SS + s0 + m8]);         \
                cp16(sptr(&Bs[st][k * 136 + m8]),                                \
                     &g_Wpb[(size_t)((k0) + k) * NQKV + n0 + m8]);               \
            }                                                                    \
            CP_COMMIT();                                                         \
        }

    QKV_LOAD(0, 0);

    for (int kt = 0; kt < 8; kt++) {
        int st = kt & 1;
        CP_WAIT0();
        __syncthreads();
        if (kt < 7) QKV_LOAD(st ^ 1, (kt + 1) * 32);

        #pragma unroll
        for (int kk = 0; kk < 2; kk++) {
            unsigned a[2][4];
            #pragma unroll
            for (int mt = 0; mt < 2; mt++) {
                int row = kk * 16 + (lane & 7) + ((lane & 16) ? 8 : 0);
                int col = wm * 32 + mt * 16 + ((lane & 8) ? 8 : 0);
                ldsm4t(a[mt][0], a[mt][1], a[mt][2], a[mt][3],
                       sptr(&As[st][row * 136 + col]));
            }
            #pragma unroll
            for (int np = 0; np < 4; np++) {
                int row = kk * 16 + (lane & 7) + ((lane & 8) ? 8 : 0);
                int col = wn * 64 + np * 16 + ((lane & 16) ? 8 : 0);
                unsigned b0, b1, b2, b3;
                ldsm4t(b0, b1, b2, b3, sptr(&Bs[st][row * 136 + col]));
                #pragma unroll
                for (int mt = 0; mt < 2; mt++) {
                    mma_f16(acc[mt][2*np],   a[mt][0], a[mt][1], a[mt][2], a[mt][3], b0, b1);
                    mma_f16(acc[mt][2*np+1], a[mt][0], a[mt][1], a[mt][2], a[mt][3], b2, b3);
                }
            }
        }
        __syncthreads();
    }
    #undef QKV_LOAD

    #pragma unroll
    for (int mt = 0; mt < 2; mt++) {
        #pragma unroll
        for (int nt = 0; nt < 8; nt++) {
            int n = n0 + wn * 64 + nt * 8 + 2 * c;
            int h = n / 192;
            int rem = n - h * 192;
            int part = rem >> 6;
            int dd = rem & 63;
            float b0v = bp[n], b1v = bp[n + 1];
            __half* dst = (part == 0) ? g_Q : (part == 1) ? g_K : g_V;
            float sc = (part == 0) ? QSCALE : 1.0f;
            #pragma unroll
            for (int half_ = 0; half_ < 2; half_++) {
                int s = s0 + wm * 32 + mt * 16 + g + half_ * 8;
                float v0 = (acc[mt][nt][half_ * 2 + 0] + b0v) * sc;
                float v1 = (acc[mt][nt][half_ * 2 + 1] + b1v) * sc;
                *(__half2*)&dst[((size_t)(b * NH + h) * SS + s) * DK + dd] =
                    __floats2half2_rn(v0, v1);
            }
        }
    }
}

// ---------------------------------------------------------------------------
// Kernel 2: flash attention. 4 warps x 32 q-rows (98.2us geometry), ones-MMA
// row sums, and fp16-accumulate S-MMA: the f16 C-fragment IS the packed
// P-fragment layout -> ex2h2 applies directly, deleting all packh ops.
// ---------------------------------------------------------------------------
#define ONESB 0x3C003C00u

extern __shared__ __align__(16) __half dynsm[];

__global__ __launch_bounds__(128, 3) void attn_kernel()
{
    __half* Qs = dynsm;                                   // [128][72]
    __half* Ksm[2] = { dynsm + 128*72,           dynsm + 128*72 + 64*72 };
    __half* Vsm[2] = { dynsm + 128*72 + 2*64*72, dynsm + 128*72 + 3*64*72 };

    const int tid = threadIdx.x, lane = tid & 31, w = tid >> 5;
    const int g = lane >> 2, c = lane & 3;
    const int qt = blockIdx.x, bh = blockIdx.y;
    const __half* Qg = g_Q + (size_t)bh * SS * DK + (size_t)qt * 128 * DK;
    const __half* Kg = g_K + (size_t)bh * SS * DK;
    const __half* Vg = g_V + (size_t)bh * SS * DK;

    #pragma unroll
    for (int r = 0; r < 8; r++) {
        int i = tid + r * 128;
        int row = i >> 3, seg = (i & 7) * 8;
        cp16(sptr(&Qs[row * 72 + seg]), Qg + row * DK + seg);
    }
    #pragma unroll
    for (int r = 0; r < 4; r++) {
        int i = tid + r * 128;
        int row = i >> 3, seg = (i & 7) * 8;
        cp16(sptr(&Ksm[0][row * 72 + seg]), Kg + row * DK + seg);
        cp16(sptr(&Vsm[0][row * 72 + seg]), Vg + row * DK + seg);
    }
    CP_COMMIT();
    CP_WAIT0();
    __syncthreads();

    const int qb = w * 32;
    unsigned qa[2][4][4];
    #pragma unroll
    for (int mt = 0; mt < 2; mt++)
        #pragma unroll
        for (int ks = 0; ks < 4; ks++) {
            int row = qb + mt * 16 + (lane & 7) + ((lane & 8) ? 8 : 0);
            int col = ks * 16 + ((lane & 16) ? 8 : 0);
            ldsm4(qa[mt][ks][0], qa[mt][ks][1], qa[mt][ks][2], qa[mt][ks][3],
                  sptr(&Qs[row * 72 + col]));
        }

    float lof[2][4] = {};
    float of[2][8][4] = {};

    for (int jt = 0; jt < 16; jt++) {
        const int buf = jt & 1;
        if (jt < 15) {
            const int nb = buf ^ 1;
            const __half* Kn = Kg + (size_t)(jt + 1) * 64 * DK;
            const __half* Vn = Vg + (size_t)(jt + 1) * 64 * DK;
            #pragma unroll
            for (int r = 0; r < 4; r++) {
                int i = tid + r * 128;
                int row = i >> 3, seg = (i & 7) * 8;
                cp16(sptr(&Ksm[nb][row * 72 + seg]), Kn + row * DK + seg);
                cp16(sptr(&Vsm[nb][row * 72 + seg]), Vn + row * DK + seg);
            }
            CP_COMMIT();
        }

        // QK^T with fp16 accumulation; C regs are packed f16x2 -> ex2 direct.
        unsigned pa[2][4][4];
        #pragma unroll
        for (int nt = 0; nt < 8; nt++) {
            unsigned s0c[2] = {0u, 0u}, s1c[2] = {0u, 0u};
            #pragma unroll
            for (int kp = 0; kp < 2; kp++) {
                int row = nt * 8 + (lane & 7);
                int col = kp * 32 + ((lane & 8) ? 8 : 0) + ((lane & 16) ? 16 : 0);
                unsigned b0, b1, b2, b3;
                ldsm4(b0, b1, b2, b3, sptr(&Ksm[buf][row * 72 + col]));
                mma_f16acc(s0c, qa[0][2*kp][0], qa[0][2*kp][1], qa[0][2*kp][2], qa[0][2*kp][3], b0, b1);
                mma_f16acc(s0c, qa[0][2*kp+1][0], qa[0][2*kp+1][1], qa[0][2*kp+1][2], qa[0][2*kp+1][3], b2, b3);
                mma_f16acc(s1c, qa[1][2*kp][0], qa[1][2*kp][1], qa[1][2*kp][2], qa[1][2*kp][3], b0, b1);
                mma_f16acc(s1c, qa[1][2*kp+1][0], qa[1][2*kp+1][1], qa[1][2*kp+1][2], qa[1][2*kp+1][3], b2, b3);
            }
            unsigned e0 = ex2h2(s0c[0]);   // mt0, row g   (cols 2c,2c+1)
            unsigned e1 = ex2h2(s0c[1]);   // mt0, row g+8
            unsigned e2 = ex2h2(s1c[0]);   // mt1, row g
            unsigned e3 = ex2h2(s1c[1]);   // mt1, row g+8
            int ks = nt >> 1;
            if (nt & 1) {
                pa[0][ks][2] = e0; pa[0][ks][3] = e1;
                pa[1][ks][2] = e2; pa[1][ks][3] = e3;
            } else {
                pa[0][ks][0] = e0; pa[0][ks][1] = e1;
                pa[1][ks][0] = e2; pa[1][ks][1] = e3;
            }
        }

        // Row sums via MMA: P x ones (fp32 accumulate)
        #pragma unroll
        for (int ks = 0; ks < 4; ks++) {
            mma_f16(lof[0], pa[0][ks][0], pa[0][ks][1], pa[0][ks][2], pa[0][ks][3], ONESB, ONESB);
            mma_f16(lof[1], pa[1][ks][0], pa[1][ks][1], pa[1][ks][2], pa[1][ks][3], ONESB, ONESB);
        }

        #pragma unroll
        for (int ks = 0; ks < 4; ks++) {
            #pragma unroll
            for (int np = 0; np < 4; np++) {
                int row = ks * 16 + (lane & 7) + ((lane & 8) ? 8 : 0);
                int col = np * 16 + ((lane & 16) ? 8 : 0);
                unsigned b0, b1, b2, b3;
                ldsm4t(b0, b1, b2, b3, sptr(&Vsm[buf][row * 72 + col]));
                #pragma unroll
                for (int mt = 0; mt < 2; mt++) {
                    mma_f16(of[mt][2*np],   pa[mt][ks][0], pa[mt][ks][1], pa[mt][ks][2], pa[mt][ks][3], b0, b1);
                    mma_f16(of[mt][2*np+1], pa[mt][ks][0], pa[mt][ks][1], pa[mt][ks][2], pa[mt][ks][3], b2, b3);
                }
            }
        }

        if (jt < 15) { CP_WAIT0(); __syncthreads(); }
    }

    const int b = bh >> 2, h = bh & 3;
    #pragma unroll
    for (int mt = 0; mt < 2; mt++) {
        float il0 = 1.0f / lof[mt][0];
        float il1 = 1.0f / lof[mt][2];
        int sg = qt * 128 + qb + mt * 16 + g;
        #pragma unroll
        for (int nt = 0; nt < 8; nt++) {
            int d = nt * 8 + 2 * c;
            *(__half2*)&g_O[((size_t)b * SS + sg) * CC + h * 64 + d] =
                __floats2half2_rn(of[mt][nt][0] * il0, of[mt][nt][1] * il0);
            *(__half2*)&g_O[((size_t)b * SS + sg + 8) * CC + h * 64 + d] =
                __floats2half2_rn(of[mt][nt][2] * il1, of[mt][nt][3] * il1);
        }
    }
}

// ---------------------------------------------------------------------------
// Kernel 3: out projection + bias + residual. m128 x n128, K=256 -> 256 CTAs.
// ---------------------------------------------------------------------------
#define SGW 132

__global__ __launch_bounds__(256, 2) void out_gemm_kernel(
    const float* __restrict__ bo, const float* __restrict__ x,
    float* __restrict__ out)
{
    __shared__ __align__(16) __half As[2][128 * 40];   // 20.5KB; aliased by Sg
    __shared__ __align__(16) __half Bs[2][32 * 136];   // 17.4KB

    float* Sg = reinterpret_cast<float*>(As);          // 32*132*4 = 16.9KB

    const int tid = threadIdx.x, lane = tid & 31, w = tid >> 5;
    const int wm = w & 3, wn = w >> 2;
    const int m0 = blockIdx.y * 128, n0 = blockIdx.x * 128;
    const int b = m0 >> 10, s0 = m0 & 1023;

    float acc[2][8][4] = {};

    #define OUT_LOAD(st, k0)                                                     \
        {                                                                        \
            _Pragma("unroll")                                                    \
            for (int r = 0; r < 2; r++) {                                        \
                int i = tid + r * 256;                                           \
                int m = i >> 2, k8 = (i & 3) * 8;                                \
                cp16(sptr(&As[st][m * 40 + k8]),                                 \
                     &g_O[(size_t)(m0 + m) * CC + (k0) + k8]);                   \
                int kb = i >> 4, n8 = (i & 15) * 8;                              \
                cp16(sptr(&Bs[st][kb * 136 + n8]),                               \
                     &g_Wob[(size_t)((k0) + kb) * CC + n0 + n8]);                \
            }                                                                    \
            CP_COMMIT();                                                         \
        }

    OUT_LOAD(0, 0);

    for (int kt = 0; kt < 8; kt++) {
        int st = kt & 1;
        CP_WAIT0();
        __syncthreads();
        if (kt < 7) OUT_LOAD(st ^ 1, (kt + 1) * 32);

        #pragma unroll
        for (int kk = 0; kk < 2; kk++) {
            unsigned a[2][4];
            #pragma unroll
            for (int mt = 0; mt < 2; mt++) {
                int row = wm * 32 + mt * 16 + (lane & 7) + ((lane & 8) ? 8 : 0);
                int col = kk * 16 + ((lane & 16) ? 8 : 0);
                ldsm4(a[mt][0], a[mt][1], a[mt][2], a[mt][3],
                      sptr(&As[st][row * 40 + col]));
            }
            #pragma unroll
            for (int np = 0; np < 4; np++) {
                int row = kk * 16 + (lane & 7) + ((lane & 8) ? 8 : 0);
                int col = wn * 64 + np * 16 + ((lane & 16) ? 8 : 0);
                unsigned b0, b1, b2, b3;
                ldsm4t(b0, b1, b2, b3, sptr(&Bs[st][row * 136 + col]));
                #pragma unroll
                for (int mt = 0; mt < 2; mt++) {
                    mma_f16(acc[mt][2*np],   a[mt][0], a[mt][1], a[mt][2], a[mt][3], b0, b1);
                    mma_f16(acc[mt][2*np+1], a[mt][0], a[mt][1], a[mt][2], a[mt][3], b2, b3);
                }
            }
        }
        __syncthreads();
    }
    #undef OUT_LOAD

    const int g = lane >> 2, c = lane & 3;
    #pragma unroll
    for (int nh = 0; nh < 4; nh++) {
        __syncthreads();
        if (wn == (nh >> 1)) {
            #pragma unroll
            for (int mt = 0; mt < 2; mt++)
                #pragma unroll
                for (int nt4 = 0; nt4 < 4; nt4++) {
                    int nt = (nh & 1) * 4 + nt4;
                    #pragma unroll
                    for (int i = 0; i < 4; i++) {
                        int row = wm * 32 + mt * 16 + g + (i >> 1) * 8;
                        int cl = nt4 * 8 + 2 * c + (i & 1);
                        Sg[cl * SGW + row] = acc[mt][nt][i];
                    }
                }
        }
        __syncthreads();
        #pragma unroll
        for (int cr = 0; cr < 4; cr++) {
            int cl = w * 4 + cr;
            int cg = n0 + nh * 32 + cl;
            size_t gidx = ((size_t)(b * CC + cg)) * SS + s0 + lane * 4;
            float4 v = *(float4*)&Sg[cl * SGW + lane * 4];
            float4 xv = *(const float4*)&x[gidx];
            float bb = bo[cg];
            v.x += bb + xv.x; v.y += bb + xv.y;
            v.z += bb + xv.z; v.w += bb + xv.w;
            *(float4*)&out[gidx] = v;
        }
    }
}

// ---------------------------------------------------------------------------
extern "C" void kernel_launch(void* const* d_in, const int* in_sizes, int n_in,
                              void* d_out, int out_size)
{
    const float* x      = (const float*)d_in[0];
    const float* w_proj = (const float*)d_in[1];
    const float* b_proj = (const float*)d_in[2];
    const float* w_out  = (const float*)d_in[3];
    const float* b_out  = (const float*)d_in[4];
    float* out = (float*)d_out;

    (void)in_sizes; (void)n_in; (void)out_size;

    const int attn_smem = (128 * 72 + 4 * 64 * 72) * sizeof(__half); // 55,296
    cudaFuncSetAttribute(attn_kernel,
                         cudaFuncAttributeMaxDynamicSharedMemorySize, attn_smem);

    convert_kernel<<<(NX + NWP + NWO) / 1024, 256>>>(x, w_proj, w_out);
    qkv_gemm_kernel<<<dim3(NQKV / 128, (BB * SS) / 128), 256>>>(b_proj);
    attn_kernel<<<dim3(SS / 128, BB * NH), 128, attn_smem>>>();
    out_gemm_kernel<<<dim3(CC / 128, (BB * SS) / 128), 256>>>(b_out, x, out);
}

// round 17
// speedup vs baseline: 1.4732x; 1.4732x over previous
#include <cuda_runtime.h>
#include <cuda_fp16.h>
#include <math.h>

#define BB 16
#define CC 256
#define SS 1024
#define NH 4
#define DK 64
#define NQKV 768

#define NX   (BB * CC * SS)
#define NWP  (CC * NQKV)
#define NWO  (NH * DK * CC)

// log2(e)/8 folded into Q
#define QSCALE 0.1803368801111244f

__device__ __half g_Xb[NX];
__device__ __half g_Wpb[NWP];
__device__ __half g_Wob[NWO];
__device__ __half g_Q[BB * NH * SS * DK];   // [B,H,S,D], pre-scaled
__device__ __half g_K[BB * NH * SS * DK];
__device__ __half g_V[BB * NH * SS * DK];
__device__ __half g_O[BB * SS * CC];

// ---------------------------------------------------------------------------
__device__ __forceinline__ unsigned sptr(const void* p) {
    return (unsigned)__cvta_generic_to_shared(p);
}
__device__ __forceinline__ unsigned packh(float lo, float hi) {
    unsigned r;
    asm("cvt.rn.f16x2.f32 %0, %1, %2;" : "=r"(r) : "f"(hi), "f"(lo));
    return r;
}
__device__ __forceinline__ unsigned ex2h2(unsigned x) {
    unsigned r;
    asm("ex2.approx.f16x2 %0, %1;" : "=r"(r) : "r"(x));
    return r;
}
__device__ __forceinline__ void ldsm4(unsigned& r0, unsigned& r1, unsigned& r2,
                                      unsigned& r3, unsigned addr) {
    asm volatile("ldmatrix.sync.aligned.m8n8.x4.shared.b16 {%0,%1,%2,%3}, [%4];"
                 : "=r"(r0), "=r"(r1), "=r"(r2), "=r"(r3) : "r"(addr));
}
__device__ __forceinline__ void ldsm4t(unsigned& r0, unsigned& r1, unsigned& r2,
                                       unsigned& r3, unsigned addr) {
    asm volatile("ldmatrix.sync.aligned.m8n8.x4.trans.shared.b16 {%0,%1,%2,%3}, [%4];"
                 : "=r"(r0), "=r"(r1), "=r"(r2), "=r"(r3) : "r"(addr));
}
__device__ __forceinline__ void mma_f16(float* c,
    unsigned a0, unsigned a1, unsigned a2, unsigned a3, unsigned b0, unsigned b1) {
    asm volatile(
        "mma.sync.aligned.m16n8k16.row.col.f32.f16.f16.f32 "
        "{%0,%1,%2,%3}, {%4,%5,%6,%7}, {%8,%9}, {%0,%1,%2,%3};"
        : "+f"(c[0]), "+f"(c[1]), "+f"(c[2]), "+f"(c[3])
        : "r"(a0), "r"(a1), "r"(a2), "r"(a3), "r"(b0), "r"(b1));
}
__device__ __forceinline__ void cp16(unsigned dst, const void* src) {
    asm volatile("cp.async.cg.shared.global [%0], [%1], 16;\n" :: "r"(dst), "l"(src));
}
#define CP_COMMIT() asm volatile("cp.async.commit_group;\n" ::: "memory")
#define CP_WAIT0()  asm volatile("cp.async.wait_group 0;\n" ::: "memory")

// ---------------------------------------------------------------------------
// Kernel 0: fp32 -> fp16 conversion
// ---------------------------------------------------------------------------
__global__ __launch_bounds__(256) void convert_kernel(
    const float* __restrict__ x, const float* __restrict__ wp,
    const float* __restrict__ wo)
{
    long long base = ((long long)blockIdx.x * 256 + threadIdx.x) * 4;
    const float* src;
    __half* dst;
    long long off;
    if (base < NX)             { src = x;  dst = g_Xb;  off = base; }
    else if (base < NX + NWP)  { src = wp; dst = g_Wpb; off = base - NX; }
    else                       { src = wo; dst = g_Wob; off = base - NX - NWP; }
    float4 t = *(const float4*)&src[off];
    *(uint2*)&dst[off] = make_uint2(packh(t.x, t.y), packh(t.z, t.w));
}

// ---------------------------------------------------------------------------
// Kernel 1: QKV projection. 128x128x32 tiles, 2-stage cp.async, 8 warps.
// ---------------------------------------------------------------------------
__global__ __launch_bounds__(256) void qkv_gemm_kernel(const float* __restrict__ bp)
{
    __shared__ __align__(16) __half As[2][32 * 136];
    __shared__ __align__(16) __half Bs[2][32 * 136];

    const int tid = threadIdx.x, lane = tid & 31, w = tid >> 5;
    const int wm = w & 3, wn = w >> 2;
    const int g = lane >> 2, c = lane & 3;
    const int m0 = blockIdx.y * 128, n0 = blockIdx.x * 128;
    const int b = m0 >> 10, s0 = m0 & 1023;

    float acc[2][8][4] = {};

    #define QKV_LOAD(st, k0)                                                     \
        {                                                                        \
            _Pragma("unroll")                                                    \
            for (int r = 0; r < 2; r++) {                                        \
                int i = tid + r * 256;                                           \
                int k = i >> 4, m8 = (i & 15) * 8;                               \
                cp16(sptr(&As[st][k * 136 + m8]),                                \
                     &g_Xb[(size_t)(b * CC + (k0) + k) * SS + s0 + m8]);         \
                cp16(sptr(&Bs[st][k * 136 + m8]),                                \
                     &g_Wpb[(size_t)((k0) + k) * NQKV + n0 + m8]);               \
            }                                                                    \
            CP_COMMIT();                                                         \
        }

    QKV_LOAD(0, 0);

    for (int kt = 0; kt < 8; kt++) {
        int st = kt & 1;
        CP_WAIT0();
        __syncthreads();
        if (kt < 7) QKV_LOAD(st ^ 1, (kt + 1) * 32);

        #pragma unroll
        for (int kk = 0; kk < 2; kk++) {
            unsigned a[2][4];
            #pragma unroll
            for (int mt = 0; mt < 2; mt++) {
                int row = kk * 16 + (lane & 7) + ((lane & 16) ? 8 : 0);
                int col = wm * 32 + mt * 16 + ((lane & 8) ? 8 : 0);
                ldsm4t(a[mt][0], a[mt][1], a[mt][2], a[mt][3],
                       sptr(&As[st][row * 136 + col]));
            }
            #pragma unroll
            for (int np = 0; np < 4; np++) {
                int row = kk * 16 + (lane & 7) + ((lane & 8) ? 8 : 0);
                int col = wn * 64 + np * 16 + ((lane & 16) ? 8 : 0);
                unsigned b0, b1, b2, b3;
                ldsm4t(b0, b1, b2, b3, sptr(&Bs[st][row * 136 + col]));
                #pragma unroll
                for (int mt = 0; mt < 2; mt++) {
                    mma_f16(acc[mt][2*np],   a[mt][0], a[mt][1], a[mt][2], a[mt][3], b0, b1);
                    mma_f16(acc[mt][2*np+1], a[mt][0], a[mt][1], a[mt][2], a[mt][3], b2, b3);
                }
            }
        }
        __syncthreads();
    }
    #undef QKV_LOAD

    #pragma unroll
    for (int mt = 0; mt < 2; mt++) {
        #pragma unroll
        for (int nt = 0; nt < 8; nt++) {
            int n = n0 + wn * 64 + nt * 8 + 2 * c;
            int h = n / 192;
            int rem = n - h * 192;
            int part = rem >> 6;
            int dd = rem & 63;
            float b0v = bp[n], b1v = bp[n + 1];
            __half* dst = (part == 0) ? g_Q : (part == 1) ? g_K : g_V;
            float sc = (part == 0) ? QSCALE : 1.0f;
            #pragma unroll
            for (int half_ = 0; half_ < 2; half_++) {
                int s = s0 + wm * 32 + mt * 16 + g + half_ * 8;
                float v0 = (acc[mt][nt][half_ * 2 + 0] + b0v) * sc;
                float v1 = (acc[mt][nt][half_ * 2 + 1] + b1v) * sc;
                *(__half2*)&dst[((size_t)(b * NH + h) * SS + s) * DK + dd] =
                    __floats2half2_rn(v0, v1);
            }
        }
    }
}

// ---------------------------------------------------------------------------
// Kernel 2: flash attention. 4 warps x 32 q-rows; ones-MMA row sums;
// fp32-accumulate S-MMA + packh + ex2h2 (the proven 98.2us configuration).
// ---------------------------------------------------------------------------
#define ONESB 0x3C003C00u

extern __shared__ __align__(16) __half dynsm[];

__global__ __launch_bounds__(128, 3) void attn_kernel()
{
    __half* Qs = dynsm;                                   // [128][72]
    __half* Ksm[2] = { dynsm + 128*72,           dynsm + 128*72 + 64*72 };
    __half* Vsm[2] = { dynsm + 128*72 + 2*64*72, dynsm + 128*72 + 3*64*72 };

    const int tid = threadIdx.x, lane = tid & 31, w = tid >> 5;
    const int g = lane >> 2, c = lane & 3;
    const int qt = blockIdx.x, bh = blockIdx.y;
    const __half* Qg = g_Q + (size_t)bh * SS * DK + (size_t)qt * 128 * DK;
    const __half* Kg = g_K + (size_t)bh * SS * DK;
    const __half* Vg = g_V + (size_t)bh * SS * DK;

    #pragma unroll
    for (int r = 0; r < 8; r++) {
        int i = tid + r * 128;
        int row = i >> 3, seg = (i & 7) * 8;
        cp16(sptr(&Qs[row * 72 + seg]), Qg + row * DK + seg);
    }
    #pragma unroll
    for (int r = 0; r < 4; r++) {
        int i = tid + r * 128;
        int row = i >> 3, seg = (i & 7) * 8;
        cp16(sptr(&Ksm[0][row * 72 + seg]), Kg + row * DK + seg);
        cp16(sptr(&Vsm[0][row * 72 + seg]), Vg + row * DK + seg);
    }
    CP_COMMIT();
    CP_WAIT0();
    __syncthreads();

    const int qb = w * 32;
    unsigned qa[2][4][4];
    #pragma unroll
    for (int mt = 0; mt < 2; mt++)
        #pragma unroll
        for (int ks = 0; ks < 4; ks++) {
            int row = qb + mt * 16 + (lane & 7) + ((lane & 8) ? 8 : 0);
            int col = ks * 16 + ((lane & 16) ? 8 : 0);
            ldsm4(qa[mt][ks][0], qa[mt][ks][1], qa[mt][ks][2], qa[mt][ks][3],
                  sptr(&Qs[row * 72 + col]));
        }

    float lof[2][4] = {};
    float of[2][8][4] = {};

    for (int jt = 0; jt < 16; jt++) {
        const int buf = jt & 1;
        if (jt < 15) {
            const int nb = buf ^ 1;
            const __half* Kn = Kg + (size_t)(jt + 1) * 64 * DK;
            const __half* Vn = Vg + (size_t)(jt + 1) * 64 * DK;
            #pragma unroll
            for (int r = 0; r < 4; r++) {
                int i = tid + r * 128;
                int row = i >> 3, seg = (i & 7) * 8;
                cp16(sptr(&Ksm[nb][row * 72 + seg]), Kn + row * DK + seg);
                cp16(sptr(&Vsm[nb][row * 72 + seg]), Vn + row * DK + seg);
            }
            CP_COMMIT();
        }

        unsigned pa[2][4][4];
        #pragma unroll
        for (int nt = 0; nt < 8; nt++) {
            float s0f[4] = {}, s1f[4] = {};
            #pragma unroll
            for (int kp = 0; kp < 2; kp++) {
                int row = nt * 8 + (lane & 7);
                int col = kp * 32 + ((lane & 8) ? 8 : 0) + ((lane & 16) ? 16 : 0);
                unsigned b0, b1, b2, b3;
                ldsm4(b0, b1, b2, b3, sptr(&Ksm[buf][row * 72 + col]));
                mma_f16(s0f, qa[0][2*kp][0], qa[0][2*kp][1], qa[0][2*kp][2], qa[0][2*kp][3], b0, b1);
                mma_f16(s0f, qa[0][2*kp+1][0], qa[0][2*kp+1][1], qa[0][2*kp+1][2], qa[0][2*kp+1][3], b2, b3);
                mma_f16(s1f, qa[1][2*kp][0], qa[1][2*kp][1], qa[1][2*kp][2], qa[1][2*kp][3], b0, b1);
                mma_f16(s1f, qa[1][2*kp+1][0], qa[1][2*kp+1][1], qa[1][2*kp+1][2], qa[1][2*kp+1][3], b2, b3);
            }
            unsigned e0 = ex2h2(packh(s0f[0], s0f[1]));
            unsigned e1 = ex2h2(packh(s0f[2], s0f[3]));
            unsigned e2 = ex2h2(packh(s1f[0], s1f[1]));
            unsigned e3 = ex2h2(packh(s1f[2], s1f[3]));
            int ks = nt >> 1;
            if (nt & 1) {
                pa[0][ks][2] = e0; pa[0][ks][3] = e1;
                pa[1][ks][2] = e2; pa[1][ks][3] = e3;
            } else {
                pa[0][ks][0] = e0; pa[0][ks][1] = e1;
                pa[1][ks][0] = e2; pa[1][ks][1] = e3;
            }
        }

        #pragma unroll
        for (int ks = 0; ks < 4; ks++) {
            mma_f16(lof[0], pa[0][ks][0], pa[0][ks][1], pa[0][ks][2], pa[0][ks][3], ONESB, ONESB);
            mma_f16(lof[1], pa[1][ks][0], pa[1][ks][1], pa[1][ks][2], pa[1][ks][3], ONESB, ONESB);
        }

        #pragma unroll
        for (int ks = 0; ks < 4; ks++) {
            #pragma unroll
            for (int np = 0; np < 4; np++) {
                int row = ks * 16 + (lane & 7) + ((lane & 8) ? 8 : 0);
                int col = np * 16 + ((lane & 16) ? 8 : 0);
                unsigned b0, b1, b2, b3;
                ldsm4t(b0, b1, b2, b3, sptr(&Vsm[buf][row * 72 + col]));
                #pragma unroll
                for (int mt = 0; mt < 2; mt++) {
                    mma_f16(of[mt][2*np],   pa[mt][ks][0], pa[mt][ks][1], pa[mt][ks][2], pa[mt][ks][3], b0, b1);
                    mma_f16(of[mt][2*np+1], pa[mt][ks][0], pa[mt][ks][1], pa[mt][ks][2], pa[mt][ks][3], b2, b3);
                }
            }
        }

        if (jt < 15) { CP_WAIT0(); __syncthreads(); }
    }

    const int b = bh >> 2, h = bh & 3;
    #pragma unroll
    for (int mt = 0; mt < 2; mt++) {
        float il0 = 1.0f / lof[mt][0];
        float il1 = 1.0f / lof[mt][2];
        int sg = qt * 128 + qb + mt * 16 + g;
        #pragma unroll
        for (int nt = 0; nt < 8; nt++) {
            int d = nt * 8 + 2 * c;
            *(__half2*)&g_O[((size_t)b * SS + sg) * CC + h * 64 + d] =
                __floats2half2_rn(of[mt][nt][0] * il0, of[mt][nt][1] * il0);
            *(__half2*)&g_O[((size_t)b * SS + sg + 8) * CC + h * 64 + d] =
                __floats2half2_rn(of[mt][nt][2] * il1, of[mt][nt][3] * il1);
        }
    }
}

// ---------------------------------------------------------------------------
// Kernel 3: out projection + bias + residual. m128 x n128, K=256 -> 256 CTAs.
// ---------------------------------------------------------------------------
#define SGW 132

__global__ __launch_bounds__(256, 2) void out_gemm_kernel(
    const float* __restrict__ bo, const float* __restrict__ x,
    float* __restrict__ out)
{
    __shared__ __align__(16) __half As[2][128 * 40];   // 20.5KB; aliased by Sg
    __shared__ __align__(16) __half Bs[2][32 * 136];   // 17.4KB

    float* Sg = reinterpret_cast<float*>(As);          // 32*132*4 = 16.9KB

    const int tid = threadIdx.x, lane = tid & 31, w = tid >> 5;
    const int wm = w & 3, wn = w >> 2;
    const int m0 = blockIdx.y * 128, n0 = blockIdx.x * 128;
    const int b = m0 >> 10, s0 = m0 & 1023;

    float acc[2][8][4] = {};

    #define OUT_LOAD(st, k0)                                                     \
        {                                                                        \
            _Pragma("unroll")                                                    \
            for (int r = 0; r < 2; r++) {                                        \
                int i = tid + r * 256;                                           \
                int m = i >> 2, k8 = (i & 3) * 8;                                \
                cp16(sptr(&As[st][m * 40 + k8]),                                 \
                     &g_O[(size_t)(m0 + m) * CC + (k0) + k8]);                   \
                int kb = i >> 4, n8 = (i & 15) * 8;                              \
                cp16(sptr(&Bs[st][kb * 136 + n8]),                               \
                     &g_Wob[(size_t)((k0) + kb) * CC + n0 + n8]);                \
            }                                                                    \
            CP_COMMIT();                                                         \
        }

    OUT_LOAD(0, 0);

    for (int kt = 0; kt < 8; kt++) {
        int st = kt & 1;
        CP_WAIT0();
        __syncthreads();
        if (kt < 7) OUT_LOAD(st ^ 1, (kt + 1) * 32);

        #pragma unroll
        for (int kk = 0; kk < 2; kk++) {
            unsigned a[2][4];
            #pragma unroll
            for (int mt = 0; mt < 2; mt++) {
                int row = wm * 32 + mt * 16 + (lane & 7) + ((lane & 8) ? 8 : 0);
                int col = kk * 16 + ((lane & 16) ? 8 : 0);
                ldsm4(a[mt][0], a[mt][1], a[mt][2], a[mt][3],
                      sptr(&As[st][row * 40 + col]));
            }
            #pragma unroll
            for (int np = 0; np < 4; np++) {
                int row = kk * 16 + (lane & 7) + ((lane & 8) ? 8 : 0);
                int col = wn * 64 + np * 16 + ((lane & 16) ? 8 : 0);
                unsigned b0, b1, b2, b3;
                ldsm4t(b0, b1, b2, b3, sptr(&Bs[st][row * 136 + col]));
                #pragma unroll
                for (int mt = 0; mt < 2; mt++) {
                    mma_f16(acc[mt][2*np],   a[mt][0], a[mt][1], a[mt][2], a[mt][3], b0, b1);
                    mma_f16(acc[mt][2*np+1], a[mt][0], a[mt][1], a[mt][2], a[mt][3], b2, b3);
                }
            }
        }
        __syncthreads();
    }
    #undef OUT_LOAD

    const int g = lane >> 2, c = lane & 3;
    #pragma unroll
    for (int nh = 0; nh < 4; nh++) {
        __syncthreads();
        if (wn == (nh >> 1)) {
            #pragma unroll
            for (int mt = 0; mt < 2; mt++)
                #pragma unroll
                for (int nt4 = 0; nt4 < 4; nt4++) {
                    int nt = (nh & 1) * 4 + nt4;
                    #pragma unroll
                    for (int i = 0; i < 4; i++) {
                        int row = wm * 32 + mt * 16 + g + (i >> 1) * 8;
                        int cl = nt4 * 8 + 2 * c + (i & 1);
                        Sg[cl * SGW + row] = acc[mt][nt][i];
                    }
                }
        }
        __syncthreads();
        #pragma unroll
        for (int cr = 0; cr < 4; cr++) {
            int cl = w * 4 + cr;
            int cg = n0 + nh * 32 + cl;
            size_t gidx = ((size_t)(b * CC + cg)) * SS + s0 + lane * 4;
            float4 v = *(float4*)&Sg[cl * SGW + lane * 4];
            float4 xv = *(const float4*)&x[gidx];
            float bb = bo[cg];
            v.x += bb + xv.x; v.y += bb + xv.y;
            v.z += bb + xv.z; v.w += bb + xv.w;
            *(float4*)&out[gidx] = v;
        }
    }
}

// ---------------------------------------------------------------------------
extern "C" void kernel_launch(void* const* d_in, const int* in_sizes, int n_in,
                              void* d_out, int out_size)
{
    const float* x      = (const float*)d_in[0];
    const float* w_proj = (const float*)d_in[1];
    const float* b_proj = (const float*)d_in[2];
    const float* w_out  = (const float*)d_in[3];
    const float* b_out  = (const float*)d_in[4];
    float* out = (float*)d_out;

    (void)in_sizes; (void)n_in; (void)out_size;

    const int attn_smem = (128 * 72 + 4 * 64 * 72) * sizeof(__half); // 55,296
    cudaFuncSetAttribute(attn_kernel,
                         cudaFuncAttributeMaxDynamicSharedMemorySize, attn_smem);

    convert_kernel<<<(NX + NWP + NWO) / 1024, 256>>>(x, w_proj, w_out);
    qkv_gemm_kernel<<<dim3(NQKV / 128, (BB * SS) / 128), 256>>>(b_proj);
    attn_kernel<<<dim3(SS / 128, BB * NH), 128, attn_smem>>>();
    out_gemm_kernel<<<dim3(CC / 128, (BB * SS) / 128), 256>>>(b_out, x, out);
}